// round 2
// baseline (speedup 1.0000x reference)
#include <cuda_runtime.h>

#define VOCABN 32000
#define EMBEDN 256
#define H1N    512
#define KVN    128
#define BN_    32
#define SN     512
#define TN     256
#define MROWS  (BN_*TN)   // 8192

// ---------------- scratch (static device globals; no allocation) ----------------
__device__ float g_gates1[MROWS * 4 * H1N];   // 8192 x 2048
__device__ float g_h1    [MROWS * H1N];       // 8192 x 512
__device__ float g_gates2[MROWS * 4 * KVN];   // 8192 x 512
__device__ float g_h2    [MROWS * KVN];       // 8192 x 128
__device__ float g_energy[MROWS * SN];        // 8192 x 512 (attn in-place)
__device__ float g_valueT[BN_ * KVN * SN];    // 32 x 128 x 512
__device__ float g_outctx[MROWS * EMBEDN];    // 8192 x 256
// pre-rounded (tf32-in-fp32) GEMM operands
__device__ float g_Er  [VOCABN * EMBEDN];     // 32000 x 256
__device__ float g_W1r [4 * H1N * EMBEDN];    // 2048 x 256
__device__ float g_W2r [4 * KVN * H1N];       // 512 x 512
__device__ float g_keyr[BN_ * SN * KVN];      // 32 x 512 x 128

// ---------------- helpers ----------------
__device__ __forceinline__ float rnd_tf32(float x) {
    unsigned r;
    asm("cvt.rna.tf32.f32 %0, %1;" : "=r"(r) : "f"(x));
    return __uint_as_float(r);
}
__device__ __forceinline__ void cp16(void* dst_smem, const void* src) {
    unsigned s = (unsigned)__cvta_generic_to_shared(dst_smem);
    asm volatile("cp.async.cg.shared.global [%0], [%1], 16;" :: "r"(s), "l"(src));
}
__device__ __forceinline__ float sigf(float x) { return 1.f / (1.f + expf(-x)); }

// ---------------- tf32 pre-rounding copy ----------------
__global__ void round_copy4(const float4* __restrict__ src, float4* __restrict__ dst, int n4)
{
    int i = blockIdx.x * blockDim.x + threadIdx.x;
    if (i < n4) {
        float4 v = src[i];
        v.x = rnd_tf32(v.x); v.y = rnd_tf32(v.y);
        v.z = rnd_tf32(v.z); v.w = rnd_tf32(v.w);
        dst[i] = v;
    }
}

// ---------------- pipelined tiled TN GEMM: C[m,n] = sum_k A[m,k]*B[n,k] ----------------
// BM=128, BN=128, BK=32; 256 threads = 8 warps in 2(m) x 4(n); warp tile 64x32
// cp.async double-buffered. Inputs MUST already be tf32-rounded fp32.
// MODE 0: plain store (batched via z strides)
// MODE 1: A rows gathered from embedding table via token ids
// MODE 2: energy epilogue (mask cols >= enc_len[z] to -1e9)
// MODE 3: logits epilogue (add bias[m]; store out[b][m][t] with n = b*T + t)
// RSTORE: round stored values to tf32 (for outputs that feed another GEMM)
#define GBM 128
#define GBN 128
#define GBK 32
#define LDR 36            // 32 + pad4 floats -> 144B rows, 16B aligned, conflict-free frags
#define STG (128*LDR)

template <int MODE, int RSTORE>
__global__ void __launch_bounds__(256)
gemm_tn_pipe(const float* __restrict__ A, const float* __restrict__ Bmat,
             float* __restrict__ C,
             int K, int lda, int ldb, int ldc,
             long sA, long sB, long sC,
             const int* __restrict__ ytok,
             const int* __restrict__ enc_len,
             const float* __restrict__ bias)
{
    extern __shared__ float smem[];
    float* As = smem;              // 2 * STG
    float* Bs = smem + 2 * STG;    // 2 * STG

    const int tid  = threadIdx.x;
    const int warp = tid >> 5, lane = tid & 31;
    const int wm = warp >> 2, wn = warp & 3;
    const int g  = lane >> 2, tq = lane & 3;
    const int bm0 = blockIdx.y * GBM;
    const int bn0 = blockIdx.x * GBN;
    const int z   = blockIdx.z;

    const float* Ab = A    + (long)z * sA;
    const float* Bb = Bmat + (long)z * sB;

    // per-thread cp.async slots: chunk c = tid + i*256; row=c>>3, col=(c&7)*4
    int rowA[4], colc[4];
    const float* srcA[4];
    const float* srcB[4];
#pragma unroll
    for (int i = 0; i < 4; i++) {
        int c = tid + i * 256;
        int r = c >> 3;
        int col = (c & 7) << 2;
        rowA[i] = r; colc[i] = col;
        if (MODE == 1) {
            int m   = bm0 + r;
            int tok = ((m & (TN - 1)) == 0) ? 0 : ytok[m - 1];
            srcA[i] = Ab + (long)tok * lda + col;
        } else {
            srcA[i] = Ab + (long)(bm0 + r) * lda + col;
        }
        srcB[i] = Bb + (long)(bn0 + r) * ldb + col;
    }

    float acc[4][4][4];
#pragma unroll
    for (int i = 0; i < 4; i++)
#pragma unroll
        for (int j = 0; j < 4; j++)
#pragma unroll
            for (int q = 0; q < 4; q++) acc[i][j][q] = 0.f;

    const int nt = K / GBK;

    // prologue: issue stage 0
    {
        float* Ad = As; float* Bd = Bs;
#pragma unroll
        for (int i = 0; i < 4; i++) {
            cp16(Ad + rowA[i] * LDR + colc[i], srcA[i]);
            cp16(Bd + rowA[i] * LDR + colc[i], srcB[i]);
        }
        asm volatile("cp.async.commit_group;" ::: "memory");
    }

    for (int kt = 0; kt < nt; kt++) {
        if (kt + 1 < nt) {
            // issue next stage into other buffer
            int k0 = (kt + 1) * GBK;
            float* Ad = As + ((kt + 1) & 1) * STG;
            float* Bd = Bs + ((kt + 1) & 1) * STG;
#pragma unroll
            for (int i = 0; i < 4; i++) {
                cp16(Ad + rowA[i] * LDR + colc[i], srcA[i] + k0);
                cp16(Bd + rowA[i] * LDR + colc[i], srcB[i] + k0);
            }
            asm volatile("cp.async.commit_group;" ::: "memory");
            asm volatile("cp.async.wait_group 1;" ::: "memory");
        } else {
            asm volatile("cp.async.wait_group 0;" ::: "memory");
        }
        __syncthreads();

        const float* Asb = As + (kt & 1) * STG;
        const float* Bsb = Bs + (kt & 1) * STG;
#pragma unroll
        for (int kk = 0; kk < GBK; kk += 8) {
            unsigned af[4][4], bf[4][2];
#pragma unroll
            for (int mi = 0; mi < 4; mi++) {
                int r0 = wm * 64 + mi * 16 + g;
                af[mi][0] = __float_as_uint(Asb[(r0    ) * LDR + kk + tq]);
                af[mi][1] = __float_as_uint(Asb[(r0 + 8) * LDR + kk + tq]);
                af[mi][2] = __float_as_uint(Asb[(r0    ) * LDR + kk + tq + 4]);
                af[mi][3] = __float_as_uint(Asb[(r0 + 8) * LDR + kk + tq + 4]);
            }
#pragma unroll
            for (int ni = 0; ni < 4; ni++) {
                int c0 = wn * 32 + ni * 8 + g;
                bf[ni][0] = __float_as_uint(Bsb[c0 * LDR + kk + tq]);
                bf[ni][1] = __float_as_uint(Bsb[c0 * LDR + kk + tq + 4]);
            }
#pragma unroll
            for (int mi = 0; mi < 4; mi++)
#pragma unroll
                for (int ni = 0; ni < 4; ni++)
                    asm volatile(
                        "mma.sync.aligned.m16n8k8.row.col.f32.tf32.tf32.f32 "
                        "{%0,%1,%2,%3}, {%4,%5,%6,%7}, {%8,%9}, {%0,%1,%2,%3};\n"
                        : "+f"(acc[mi][ni][0]), "+f"(acc[mi][ni][1]),
                          "+f"(acc[mi][ni][2]), "+f"(acc[mi][ni][3])
                        : "r"(af[mi][0]), "r"(af[mi][1]),
                          "r"(af[mi][2]), "r"(af[mi][3]),
                          "r"(bf[ni][0]), "r"(bf[ni][1]));
        }
        __syncthreads();
    }

    // epilogue
#pragma unroll
    for (int mi = 0; mi < 4; mi++) {
#pragma unroll
        for (int ni = 0; ni < 4; ni++) {
            int row = bm0 + wm * 64 + mi * 16 + g;
            int col = bn0 + wn * 32 + ni * 8 + 2 * tq;
#pragma unroll
            for (int rr = 0; rr < 2; rr++) {
                int r = row + rr * 8;
                float v0 = acc[mi][ni][rr * 2 + 0];
                float v1 = acc[mi][ni][rr * 2 + 1];
                if (MODE == 2) {
                    int len = enc_len[z];
                    if (col     >= len) v0 = -1e9f;
                    if (col + 1 >= len) v1 = -1e9f;
                }
                if (RSTORE) { v0 = rnd_tf32(v0); v1 = rnd_tf32(v1); }
                if (MODE == 3) {
                    float bb = bias[r];
                    v0 += bb; v1 += bb;
                    int bidx = col >> 8;     // T = 256
                    int t    = col & 255;
                    *reinterpret_cast<float2*>(
                        C + (long)bidx * VOCABN * TN + (long)r * TN + t) =
                        make_float2(v0, v1);
                } else {
                    *reinterpret_cast<float2*>(
                        C + (long)z * sC + (long)r * ldc + col) =
                        make_float2(v0, v1);
                }
            }
        }
    }
}

// ---------------- elementwise LSTM-cell activation (zero state), tf32-rounded out --------
__global__ void act_lstm(const float* __restrict__ gates,
                         const float* __restrict__ b_ih,
                         const float* __restrict__ b_hh,
                         float* __restrict__ h,
                         float* __restrict__ hcopy, int H, int ldcopy, long total)
{
    long idx = (long)blockIdx.x * blockDim.x + threadIdx.x;
    if (idx >= total) return;
    int  j = (int)(idx & (H - 1));
    long m = idx / H;
    const float* gr = gates + m * 4 * H;
    float iv = gr[j]         + b_ih[j]         + b_hh[j];
    float gv = gr[2 * H + j] + b_ih[2 * H + j] + b_hh[2 * H + j];
    float ov = gr[3 * H + j] + b_ih[3 * H + j] + b_hh[3 * H + j];
    float c  = sigf(iv) * tanhf(gv);
    float hv = rnd_tf32(sigf(ov) * tanhf(c));
    h[m * H + j] = hv;
    if (hcopy) hcopy[m * ldcopy + j] = hv;
}

// ---------------- per-row softmax over S=512, in place, tf32-rounded out ----------------
__global__ void softmax_rows(float* __restrict__ e)
{
    const int row = blockIdx.x;
    float* p = e + (long)row * SN;
    __shared__ float red[128];
    int tid = threadIdx.x;
    float v0 = p[tid], v1 = p[tid + 128], v2 = p[tid + 256], v3 = p[tid + 384];
    float mx = fmaxf(fmaxf(v0, v1), fmaxf(v2, v3));
    red[tid] = mx; __syncthreads();
    for (int st = 64; st > 0; st >>= 1) {
        if (tid < st) red[tid] = fmaxf(red[tid], red[tid + st]);
        __syncthreads();
    }
    mx = red[0]; __syncthreads();
    v0 = expf(v0 - mx); v1 = expf(v1 - mx); v2 = expf(v2 - mx); v3 = expf(v3 - mx);
    float s = v0 + v1 + v2 + v3;
    red[tid] = s; __syncthreads();
    for (int st = 64; st > 0; st >>= 1) {
        if (tid < st) red[tid] += red[tid + st];
        __syncthreads();
    }
    float inv = 1.f / red[0];
    p[tid]       = rnd_tf32(v0 * inv);
    p[tid + 128] = rnd_tf32(v1 * inv);
    p[tid + 256] = rnd_tf32(v2 * inv);
    p[tid + 384] = rnd_tf32(v3 * inv);
}

// ---------------- value transpose: (B,S,KV) -> (B,KV,S), tf32-rounded ----------------
__global__ void transpose_v(const float* __restrict__ v, float* __restrict__ vt)
{
    __shared__ float tile[32][33];
    int b  = blockIdx.z;
    int s0 = blockIdx.y * 32, v0 = blockIdx.x * 32;
    int x = threadIdx.x, y = threadIdx.y;   // 32 x 8
#pragma unroll
    for (int i = 0; i < 32; i += 8)
        tile[y + i][x] = v[((long)b * SN + s0 + y + i) * KVN + v0 + x];
    __syncthreads();
#pragma unroll
    for (int i = 0; i < 32; i += 8)
        vt[((long)b * KVN + v0 + y + i) * SN + s0 + x] = rnd_tf32(tile[x][y + i]);
}

// ---------------- launch ----------------
extern "C" void kernel_launch(void* const* d_in, const int* in_sizes, int n_in,
                              void* d_out, int out_size)
{
    const float* key   = (const float*)d_in[0];
    const float* value = (const float*)d_in[1];
    const int*   elen  = (const int*)  d_in[2];
    const int*   y     = (const int*)  d_in[3];
    const float* E     = (const float*)d_in[4];
    const float* W1    = (const float*)d_in[5];
    const float* bi1   = (const float*)d_in[6];
    const float* bh1   = (const float*)d_in[7];
    const float* W2    = (const float*)d_in[8];
    const float* bi2   = (const float*)d_in[9];
    const float* bh2   = (const float*)d_in[10];
    const float* bout  = (const float*)d_in[11];
    float*       out   = (float*)d_out;

    float *gates1, *h1p, *gates2, *h2p, *energy, *valueT, *outctx;
    float *Er, *W1r, *W2r, *keyr;
    cudaGetSymbolAddress((void**)&gates1, g_gates1);
    cudaGetSymbolAddress((void**)&h1p,    g_h1);
    cudaGetSymbolAddress((void**)&gates2, g_gates2);
    cudaGetSymbolAddress((void**)&h2p,    g_h2);
    cudaGetSymbolAddress((void**)&energy, g_energy);
    cudaGetSymbolAddress((void**)&valueT, g_valueT);
    cudaGetSymbolAddress((void**)&outctx, g_outctx);
    cudaGetSymbolAddress((void**)&Er,     g_Er);
    cudaGetSymbolAddress((void**)&W1r,    g_W1r);
    cudaGetSymbolAddress((void**)&W2r,    g_W2r);
    cudaGetSymbolAddress((void**)&keyr,   g_keyr);

    const int SMEMB = 4 * STG * (int)sizeof(float);  // 73728 bytes
    cudaFuncSetAttribute(gemm_tn_pipe<0,0>, cudaFuncAttributeMaxDynamicSharedMemorySize, SMEMB);
    cudaFuncSetAttribute(gemm_tn_pipe<0,1>, cudaFuncAttributeMaxDynamicSharedMemorySize, SMEMB);
    cudaFuncSetAttribute(gemm_tn_pipe<1,0>, cudaFuncAttributeMaxDynamicSharedMemorySize, SMEMB);
    cudaFuncSetAttribute(gemm_tn_pipe<2,0>, cudaFuncAttributeMaxDynamicSharedMemorySize, SMEMB);
    cudaFuncSetAttribute(gemm_tn_pipe<3,0>, cudaFuncAttributeMaxDynamicSharedMemorySize, SMEMB);

    // 0) pre-round static GEMM operands to tf32
    round_copy4<<<(VOCABN * EMBEDN / 4 + 255) / 256, 256>>>((const float4*)E,  (float4*)Er,  VOCABN * EMBEDN / 4);
    round_copy4<<<(4 * H1N * EMBEDN / 4 + 255) / 256, 256>>>((const float4*)W1, (float4*)W1r, 4 * H1N * EMBEDN / 4);
    round_copy4<<<(4 * KVN * H1N / 4 + 255) / 256, 256>>>((const float4*)W2, (float4*)W2r, 4 * KVN * H1N / 4);
    round_copy4<<<(BN_ * SN * KVN / 4 + 255) / 256, 256>>>((const float4*)key,(float4*)keyr, BN_ * SN * KVN / 4);

    // 1) gates1 = embed(tokens) @ W1^T     (M=8192, N=2048, K=256)
    gemm_tn_pipe<1,0><<<dim3(2048 / GBN, MROWS / GBM, 1), 256, SMEMB>>>(
        Er, W1r, gates1, EMBEDN, EMBEDN, EMBEDN, 4 * H1N,
        0, 0, 0, y, nullptr, nullptr);

    // 2) h1 = lstm_act(gates1)
    {
        long total = (long)MROWS * H1N;
        act_lstm<<<(unsigned)((total + 255) / 256), 256>>>(
            gates1, bi1, bh1, h1p, nullptr, H1N, 0, total);
    }

    // 3) gates2 = h1 @ W2^T                (M=8192, N=512, K=512)
    gemm_tn_pipe<0,0><<<dim3(512 / GBN, MROWS / GBM, 1), 256, SMEMB>>>(
        h1p, W2r, gates2, H1N, H1N, H1N, 4 * KVN,
        0, 0, 0, nullptr, nullptr, nullptr);

    // 4) h2 = lstm_act(gates2); also copy into out_ctx[:, 0:128]
    {
        long total = (long)MROWS * KVN;
        act_lstm<<<(unsigned)((total + 255) / 256), 256>>>(
            gates2, bi2, bh2, h2p, outctx, KVN, EMBEDN, total);
    }

    // 5) valueT[b][v][s] = value[b][s][v]
    transpose_v<<<dim3(KVN / 32, SN / 32, BN_), dim3(32, 8)>>>(value, valueT);

    // 6) energy[b,t,s] = h2[b,t,:] . key[b,s,:], masked   (per b: M=256, N=512, K=128)
    gemm_tn_pipe<2,0><<<dim3(SN / GBN, TN / GBM, BN_), 256, SMEMB>>>(
        h2p, keyr, energy, KVN, KVN, KVN, SN,
        (long)TN * KVN, (long)SN * KVN, (long)TN * SN,
        nullptr, elen, nullptr);

    // 7) softmax over s
    softmax_rows<<<MROWS, 128>>>(energy);

    // 8) context = attn @ valueT -> out_ctx[:, 128:256]   (per b: M=256, N=128, K=512)
    gemm_tn_pipe<0,1><<<dim3(KVN / GBN, TN / GBM, BN_), 256, SMEMB>>>(
        energy, valueT, outctx + KVN, SN, SN, SN, EMBEDN,
        (long)TN * SN, (long)KVN * SN, (long)TN * EMBEDN,
        nullptr, nullptr, nullptr);

    // 9) logits = E @ out_ctx^T + b_out, stored as out[b][v][t]
    //    (M=32000, N=8192, K=256)
    gemm_tn_pipe<3,0><<<dim3(MROWS / GBN, VOCABN / GBM, 1), 256, SMEMB>>>(
        Er, outctx, out, EMBEDN, EMBEDN, EMBEDN, 0,
        0, 0, 0, nullptr, nullptr, bout);

    (void)in_sizes; (void)n_in; (void)out_size;
}

// round 5
// speedup vs baseline: 1.6394x; 1.6394x over previous
#include <cuda_runtime.h>
#include <cuda_fp16.h>
#include <cstdint>

#define VOCABN 32000
#define EMBEDN 256
#define H1N    512
#define KVN    128
#define BN_    32
#define SN     512
#define TN     256
#define MROWS  (BN_*TN)   // 8192

// ---------------- scratch (static device globals; no allocation) ----------------
__device__ float  g_gates1[MROWS * 4 * H1N];     // fp32
__device__ float  g_gates2[MROWS * 4 * KVN];     // fp32
__device__ float  g_energy[MROWS * SN];          // fp32
__device__ __half g_Eh  [VOCABN * EMBEDN];
__device__ __half g_W1h [4 * H1N * EMBEDN];
__device__ __half g_W2h [4 * KVN * H1N];
__device__ __half g_keyh[BN_ * SN * KVN];
__device__ __half g_h1h [MROWS * H1N];
__device__ __half g_h2h [MROWS * KVN];
__device__ __half g_attnh[MROWS * SN];
__device__ __half g_valueTh[BN_ * KVN * SN];
__device__ __half g_outctxh[MROWS * EMBEDN];

// ---------------- helpers ----------------
__device__ __forceinline__ void cp16(void* dst_smem, const void* src) {
    unsigned s = (unsigned)__cvta_generic_to_shared(dst_smem);
    asm volatile("cp.async.cg.shared.global [%0], [%1], 16;" :: "r"(s), "l"(src));
}
__device__ __forceinline__ float sigf(float x) { return 1.f / (1.f + expf(-x)); }

// ---------------- fp32 -> fp16 convert ----------------
__global__ void conv_h4(const float4* __restrict__ src, uint2* __restrict__ dst, int n4)
{
    int i = blockIdx.x * blockDim.x + threadIdx.x;
    if (i < n4) {
        float4 v = src[i];
        __half2 h0 = __floats2half2_rn(v.x, v.y);
        __half2 h1 = __floats2half2_rn(v.z, v.w);
        uint2 o;
        o.x = *reinterpret_cast<unsigned*>(&h0);
        o.y = *reinterpret_cast<unsigned*>(&h1);
        dst[i] = o;
    }
}

// ---------------- fp16 tiled TN GEMM: C[m,n] = sum_k A[m,k]*B[n,k] --------------
// BM=BN=128, BK=32; 256 threads = 8 warps (2m x 4n); warp tile 64x32.
// cp.async double-buffered; ldmatrix (non-trans for BOTH operands: each is
// row-major with K contiguous); mma.m16n8k16 f16->f32.
// MODE 0: plain store (batched via z strides)
// MODE 1: A rows gathered from embedding table via token ids
// MODE 2: energy epilogue (mask cols >= enc_len[z] to -1e9)
// MODE 3: logits epilogue (add bias[m]; store out[b][m][t], n = b*T + t)
// OUTH  : store output as fp16 (for operands feeding another GEMM)
#define GBM 128
#define GBN 128
#define GBK 32
#define LDH 40                 // halves per smem row: 32 data + 8 pad -> 80B stride
#define HSTG (128 * LDH)       // halves per tile buffer

template <int MODE, int OUTH>
__global__ void __launch_bounds__(256)
gemm_h(const __half* __restrict__ A, const __half* __restrict__ Bmat,
       void* __restrict__ Cv,
       int K, int lda, int ldb, int ldc,
       long sA, long sB, long sC,
       const int* __restrict__ ytok,
       const int* __restrict__ enc_len,
       const float* __restrict__ bias)
{
    __shared__ __half As[2][HSTG];
    __shared__ __half Bs[2][HSTG];

    const int tid  = threadIdx.x;
    const int warp = tid >> 5, lane = tid & 31;
    const int wm = warp >> 2, wn = warp & 3;
    const int g  = lane >> 2, tq = lane & 3;
    const int quad = lane >> 3, lr = lane & 7;
    const int bm0 = blockIdx.y * GBM;
    const int bn0 = blockIdx.x * GBN;
    const int z   = blockIdx.z;

    const __half* Ab = A    + (long)z * sA;
    const __half* Bb = Bmat + (long)z * sB;

    // cp.async mapping: 512 16B-chunks per matrix per stage; 2 per thread each
    int rowA[2], segA[2];
    const __half* srcA[2];
    const __half* srcB[2];
#pragma unroll
    for (int i = 0; i < 2; i++) {
        int c   = tid + i * 256;         // 0..511
        int r   = c >> 2;                // row 0..127
        int seg = c & 3;                 // 16B segment (8 halves)
        rowA[i] = r; segA[i] = seg;
        if (MODE == 1) {
            int m   = bm0 + r;
            int tok = ((m & (TN - 1)) == 0) ? 0 : ytok[m - 1];
            srcA[i] = Ab + (long)tok * lda + seg * 8;
        } else {
            srcA[i] = Ab + (long)(bm0 + r) * lda + seg * 8;
        }
        srcB[i] = Bb + (long)(bn0 + r) * ldb + seg * 8;
    }

    float acc[4][4][4];
#pragma unroll
    for (int i = 0; i < 4; i++)
#pragma unroll
        for (int j = 0; j < 4; j++)
#pragma unroll
            for (int q = 0; q < 4; q++) acc[i][j][q] = 0.f;

    const int nt = K / GBK;

    // prologue: stage 0
#pragma unroll
    for (int i = 0; i < 2; i++) {
        cp16(&As[0][rowA[i] * LDH + segA[i] * 8], srcA[i]);
        cp16(&Bs[0][rowA[i] * LDH + segA[i] * 8], srcB[i]);
    }
    asm volatile("cp.async.commit_group;" ::: "memory");

    for (int kt = 0; kt < nt; kt++) {
        if (kt + 1 < nt) {
            int k0 = (kt + 1) * GBK;
            int nb = (kt + 1) & 1;
#pragma unroll
            for (int i = 0; i < 2; i++) {
                cp16(&As[nb][rowA[i] * LDH + segA[i] * 8], srcA[i] + k0);
                cp16(&Bs[nb][rowA[i] * LDH + segA[i] * 8], srcB[i] + k0);
            }
            asm volatile("cp.async.commit_group;" ::: "memory");
            asm volatile("cp.async.wait_group 1;" ::: "memory");
        } else {
            asm volatile("cp.async.wait_group 0;" ::: "memory");
        }
        __syncthreads();

        const __half* Asb = As[kt & 1];
        const __half* Bsb = Bs[kt & 1];

#pragma unroll
        for (int kk = 0; kk < GBK; kk += 16) {
            unsigned af[4][4], bf[4][2];
#pragma unroll
            for (int mi = 0; mi < 4; mi++) {
                int row = wm * 64 + mi * 16 + lr + (quad & 1) * 8;
                int col = kk + (quad >> 1) * 8;
                unsigned addr = (unsigned)__cvta_generic_to_shared(
                    &Asb[row * LDH + col]);
                asm volatile(
                    "ldmatrix.sync.aligned.m8n8.x4.shared.b16 {%0,%1,%2,%3}, [%4];"
                    : "=r"(af[mi][0]), "=r"(af[mi][1]),
                      "=r"(af[mi][2]), "=r"(af[mi][3]) : "r"(addr));
            }
#pragma unroll
            for (int np = 0; np < 2; np++) {
                int row = wn * 32 + np * 16 + lr + (quad & 1) * 8;
                int col = kk + (quad >> 1) * 8;
                unsigned addr = (unsigned)__cvta_generic_to_shared(
                    &Bsb[row * LDH + col]);
                unsigned r0, r1, r2, r3;
                // NON-trans: B tile is [n][k] with k contiguous; lane gets
                // consecutive-k pairs at fixed n, exactly the mma B fragment.
                asm volatile(
                    "ldmatrix.sync.aligned.m8n8.x4.shared.b16 {%0,%1,%2,%3}, [%4];"
                    : "=r"(r0), "=r"(r1), "=r"(r2), "=r"(r3) : "r"(addr));
                bf[2 * np + 0][0] = r0; bf[2 * np + 0][1] = r2;
                bf[2 * np + 1][0] = r1; bf[2 * np + 1][1] = r3;
            }
#pragma unroll
            for (int mi = 0; mi < 4; mi++)
#pragma unroll
                for (int ni = 0; ni < 4; ni++)
                    asm volatile(
                        "mma.sync.aligned.m16n8k16.row.col.f32.f16.f16.f32 "
                        "{%0,%1,%2,%3}, {%4,%5,%6,%7}, {%8,%9}, {%0,%1,%2,%3};\n"
                        : "+f"(acc[mi][ni][0]), "+f"(acc[mi][ni][1]),
                          "+f"(acc[mi][ni][2]), "+f"(acc[mi][ni][3])
                        : "r"(af[mi][0]), "r"(af[mi][1]),
                          "r"(af[mi][2]), "r"(af[mi][3]),
                          "r"(bf[ni][0]), "r"(bf[ni][1]));
        }
        __syncthreads();
    }

    // ---------------- epilogue ----------------
#pragma unroll
    for (int mi = 0; mi < 4; mi++) {
#pragma unroll
        for (int ni = 0; ni < 4; ni++) {
            int row = bm0 + wm * 64 + mi * 16 + g;
            int col = bn0 + wn * 32 + ni * 8 + 2 * tq;
#pragma unroll
            for (int rr = 0; rr < 2; rr++) {
                int r = row + rr * 8;
                float v0 = acc[mi][ni][rr * 2 + 0];
                float v1 = acc[mi][ni][rr * 2 + 1];
                if (MODE == 2) {
                    int len = enc_len[z];
                    if (col     >= len) v0 = -1e9f;
                    if (col + 1 >= len) v1 = -1e9f;
                }
                if (MODE == 3) {
                    float bb = bias[r];
                    v0 += bb; v1 += bb;
                    int bidx = col >> 8;     // T = 256
                    int t    = col & 255;
                    *reinterpret_cast<float2*>(
                        (float*)Cv + (long)bidx * VOCABN * TN + (long)r * TN + t) =
                        make_float2(v0, v1);
                } else if (OUTH) {
                    __half2 h = __floats2half2_rn(v0, v1);
                    *reinterpret_cast<__half2*>(
                        (__half*)Cv + (long)z * sC + (long)r * ldc + col) = h;
                } else {
                    *reinterpret_cast<float2*>(
                        (float*)Cv + (long)z * sC + (long)r * ldc + col) =
                        make_float2(v0, v1);
                }
            }
        }
    }
}

// ---------------- elementwise LSTM-cell activation (zero state), fp16 out --------
__global__ void act_lstm(const float* __restrict__ gates,
                         const float* __restrict__ b_ih,
                         const float* __restrict__ b_hh,
                         __half* __restrict__ h,
                         __half* __restrict__ hcopy, int H, int ldcopy, long total)
{
    long idx = (long)blockIdx.x * blockDim.x + threadIdx.x;
    if (idx >= total) return;
    int  j = (int)(idx & (H - 1));
    long m = idx / H;
    const float* gr = gates + m * 4 * H;
    float iv = gr[j]         + b_ih[j]         + b_hh[j];
    float gv = gr[2 * H + j] + b_ih[2 * H + j] + b_hh[2 * H + j];
    float ov = gr[3 * H + j] + b_ih[3 * H + j] + b_hh[3 * H + j];
    float c  = sigf(iv) * tanhf(gv);
    __half hv = __float2half_rn(sigf(ov) * tanhf(c));
    h[m * H + j] = hv;
    if (hcopy) hcopy[m * ldcopy + j] = hv;
}

// ---------------- per-row softmax over S=512: fp32 in, fp16 out ----------------
__global__ void softmax_rows(const float* __restrict__ e, __half* __restrict__ a)
{
    const int row = blockIdx.x;
    const float* p = e + (long)row * SN;
    __half* q = a + (long)row * SN;
    __shared__ float red[128];
    int tid = threadIdx.x;
    float v0 = p[tid], v1 = p[tid + 128], v2 = p[tid + 256], v3 = p[tid + 384];
    float mx = fmaxf(fmaxf(v0, v1), fmaxf(v2, v3));
    red[tid] = mx; __syncthreads();
    for (int st = 64; st > 0; st >>= 1) {
        if (tid < st) red[tid] = fmaxf(red[tid], red[tid + st]);
        __syncthreads();
    }
    mx = red[0]; __syncthreads();
    v0 = expf(v0 - mx); v1 = expf(v1 - mx); v2 = expf(v2 - mx); v3 = expf(v3 - mx);
    float s = v0 + v1 + v2 + v3;
    red[tid] = s; __syncthreads();
    for (int st = 64; st > 0; st >>= 1) {
        if (tid < st) red[tid] += red[tid + st];
        __syncthreads();
    }
    float inv = 1.f / red[0];
    q[tid]       = __float2half_rn(v0 * inv);
    q[tid + 128] = __float2half_rn(v1 * inv);
    q[tid + 256] = __float2half_rn(v2 * inv);
    q[tid + 384] = __float2half_rn(v3 * inv);
}

// ---------------- value transpose: (B,S,KV) fp32 -> (B,KV,S) fp16 ----------------
__global__ void transpose_v(const float* __restrict__ v, __half* __restrict__ vt)
{
    __shared__ float tile[32][33];
    int b  = blockIdx.z;
    int s0 = blockIdx.y * 32, v0 = blockIdx.x * 32;
    int x = threadIdx.x, y = threadIdx.y;   // 32 x 8
#pragma unroll
    for (int i = 0; i < 32; i += 8)
        tile[y + i][x] = v[((long)b * SN + s0 + y + i) * KVN + v0 + x];
    __syncthreads();
#pragma unroll
    for (int i = 0; i < 32; i += 8)
        vt[((long)b * KVN + v0 + y + i) * SN + s0 + x] = __float2half_rn(tile[x][y + i]);
}

// ---------------- launch ----------------
extern "C" void kernel_launch(void* const* d_in, const int* in_sizes, int n_in,
                              void* d_out, int out_size)
{
    const float* key   = (const float*)d_in[0];
    const float* value = (const float*)d_in[1];
    const int*   elen  = (const int*)  d_in[2];
    const int*   y     = (const int*)  d_in[3];
    const float* E     = (const float*)d_in[4];
    const float* W1    = (const float*)d_in[5];
    const float* bi1   = (const float*)d_in[6];
    const float* bh1   = (const float*)d_in[7];
    const float* W2    = (const float*)d_in[8];
    const float* bi2   = (const float*)d_in[9];
    const float* bh2   = (const float*)d_in[10];
    const float* bout  = (const float*)d_in[11];
    float*       out   = (float*)d_out;

    float  *gates1, *gates2, *energy;
    __half *Eh, *W1h, *W2h, *keyh, *h1h, *h2h, *attnh, *valueTh, *outctxh;
    cudaGetSymbolAddress((void**)&gates1, g_gates1);
    cudaGetSymbolAddress((void**)&gates2, g_gates2);
    cudaGetSymbolAddress((void**)&energy, g_energy);
    cudaGetSymbolAddress((void**)&Eh,     g_Eh);
    cudaGetSymbolAddress((void**)&W1h,    g_W1h);
    cudaGetSymbolAddress((void**)&W2h,    g_W2h);
    cudaGetSymbolAddress((void**)&keyh,   g_keyh);
    cudaGetSymbolAddress((void**)&h1h,    g_h1h);
    cudaGetSymbolAddress((void**)&h2h,    g_h2h);
    cudaGetSymbolAddress((void**)&attnh,  g_attnh);
    cudaGetSymbolAddress((void**)&valueTh,g_valueTh);
    cudaGetSymbolAddress((void**)&outctxh,g_outctxh);

    // 0) convert static GEMM operands to fp16
    conv_h4<<<(VOCABN * EMBEDN / 4 + 255) / 256, 256>>>((const float4*)E,  (uint2*)Eh,  VOCABN * EMBEDN / 4);
    conv_h4<<<(4 * H1N * EMBEDN / 4 + 255) / 256, 256>>>((const float4*)W1, (uint2*)W1h, 4 * H1N * EMBEDN / 4);
    conv_h4<<<(4 * KVN * H1N / 4 + 255) / 256, 256>>>((const float4*)W2, (uint2*)W2h, 4 * KVN * H1N / 4);
    conv_h4<<<(BN_ * SN * KVN / 4 + 255) / 256, 256>>>((const float4*)key,(uint2*)keyh, BN_ * SN * KVN / 4);

    // 1) gates1 = embed(tokens) @ W1^T     (M=8192, N=2048, K=256) fp32 out
    gemm_h<1,0><<<dim3(2048 / GBN, MROWS / GBM, 1), 256>>>(
        Eh, W1h, gates1, EMBEDN, EMBEDN, EMBEDN, 4 * H1N,
        0, 0, 0, y, nullptr, nullptr);

    // 2) h1 = lstm_act(gates1) -> fp16
    {
        long total = (long)MROWS * H1N;
        act_lstm<<<(unsigned)((total + 255) / 256), 256>>>(
            gates1, bi1, bh1, h1h, nullptr, H1N, 0, total);
    }

    // 3) gates2 = h1 @ W2^T                (M=8192, N=512, K=512) fp32 out
    gemm_h<0,0><<<dim3(512 / GBN, MROWS / GBM, 1), 256>>>(
        h1h, W2h, gates2, H1N, H1N, H1N, 4 * KVN,
        0, 0, 0, nullptr, nullptr, nullptr);

    // 4) h2 = lstm_act(gates2) -> fp16; copy into out_ctx[:, 0:128]
    {
        long total = (long)MROWS * KVN;
        act_lstm<<<(unsigned)((total + 255) / 256), 256>>>(
            gates2, bi2, bh2, h2h, outctxh, KVN, EMBEDN, total);
    }

    // 5) valueT (fp16)
    transpose_v<<<dim3(KVN / 32, SN / 32, BN_), dim3(32, 8)>>>(value, valueTh);

    // 6) energy[b,t,s] = h2 . key, masked  (per b: M=256, N=512, K=128) fp32 out
    gemm_h<2,0><<<dim3(SN / GBN, TN / GBM, BN_), 256>>>(
        h2h, keyh, energy, KVN, KVN, KVN, SN,
        (long)TN * KVN, (long)SN * KVN, (long)TN * SN,
        nullptr, elen, nullptr);

    // 7) softmax -> fp16 attn
    softmax_rows<<<MROWS, 128>>>(energy, attnh);

    // 8) context = attn @ valueT -> out_ctx[:, 128:256] fp16
    gemm_h<0,1><<<dim3(KVN / GBN, TN / GBM, BN_), 256>>>(
        attnh, valueTh, outctxh + KVN, SN, SN, SN, EMBEDN,
        (long)TN * SN, (long)KVN * SN, (long)TN * EMBEDN,
        nullptr, nullptr, nullptr);

    // 9) logits = E @ out_ctx^T + b_out -> out[b][v][t]  (M=32000, N=8192, K=256)
    gemm_h<3,0><<<dim3(MROWS / GBN, VOCABN / GBM, 1), 256>>>(
        Eh, outctxh, out, EMBEDN, EMBEDN, EMBEDN, 0,
        0, 0, 0, nullptr, nullptr, bout);

    (void)in_sizes; (void)n_in; (void)out_size;
}